// round 2
// baseline (speedup 1.0000x reference)
#include <cuda_runtime.h>
#include <math.h>

// Problem constants
#define BB   64
#define NTOK 197
#define CCH  768
#define HH   12
#define DHH  64
#define C3   2304
#define MTOK (BB * NTOK)          // 12608
#define QSCALE 0.125f             // 64^-0.5

// -------- device scratch (static __device__ allocation is allowed) --------
__device__ float g_q[(size_t)BB * HH * NTOK * DHH];                 // 38.7 MB
__device__ float g_k[(size_t)BB * HH * NTOK * DHH];
__device__ float g_v[(size_t)BB * HH * NTOK * DHH];
__device__ float g_sc[(size_t)BB * HH * NTOK * NTOK];               // 119 MB
__device__ float g_am[(size_t)BB * HH * NTOK * NTOK];               // 119 MB
__device__ float g_ctx[(size_t)MTOK * CCH];                         // 38.7 MB

// ============================================================================
// K1: qkv = x @ qkv_w^T  (+ (q_bias,0,v_bias))  * ssf_scale + ssf_shift
//     then scatter to g_q (scaled by QSCALE), g_k, g_v  in [B,H,N,DH]
// M = 12608 (197 tiles of 64), N = 2304 (36 tiles of 64), K = 768
// ============================================================================
__global__ __launch_bounds__(256) void qkv_gemm(
    const float* __restrict__ x, const float* __restrict__ w,
    const float* __restrict__ qb, const float* __restrict__ vb,
    const float* __restrict__ ssc, const float* __restrict__ ssh)
{
    __shared__ float As[16][64];
    __shared__ float Bs[16][64];

    const int tid = threadIdx.x;
    const int m0 = blockIdx.y * 64;
    const int j0 = blockIdx.x * 64;

    const int tr = tid / 16;      // 0..15 (rows, 4 each)
    const int tc = tid % 16;      // 0..15 (cols, 4 each)
    const int lr = tid / 4;       // 0..63 load row
    const int lc = tid % 4;       // float4 slot along K

    const float* xrow = x + (size_t)(m0 + lr) * CCH + lc * 4;
    const float* wrow = w + (size_t)(j0 + lr) * CCH + lc * 4;

    float acc[4][4] = {};

    for (int k0 = 0; k0 < CCH; k0 += 16) {
        float4 av = *(const float4*)(xrow + k0);
        float4 bv = *(const float4*)(wrow + k0);
        As[lc * 4 + 0][lr] = av.x; As[lc * 4 + 1][lr] = av.y;
        As[lc * 4 + 2][lr] = av.z; As[lc * 4 + 3][lr] = av.w;
        Bs[lc * 4 + 0][lr] = bv.x; Bs[lc * 4 + 1][lr] = bv.y;
        Bs[lc * 4 + 2][lr] = bv.z; Bs[lc * 4 + 3][lr] = bv.w;
        __syncthreads();
#pragma unroll
        for (int kk = 0; kk < 16; kk++) {
            float4 a4 = *(const float4*)&As[kk][tr * 4];
            float4 b4 = *(const float4*)&Bs[kk][tc * 4];
            float a[4] = {a4.x, a4.y, a4.z, a4.w};
            float b[4] = {b4.x, b4.y, b4.z, b4.w};
#pragma unroll
            for (int i = 0; i < 4; i++)
#pragma unroll
                for (int j = 0; j < 4; j++)
                    acc[i][j] = fmaf(a[i], b[j], acc[i][j]);
        }
        __syncthreads();
    }

#pragma unroll
    for (int i = 0; i < 4; i++) {
        const int m = m0 + tr * 4 + i;
        const int b = m / NTOK, n = m % NTOK;
#pragma unroll
        for (int j = 0; j < 4; j++) {
            const int jj = j0 + tc * 4 + j;
            const int part = jj / CCH;      // 0=q 1=k 2=v
            const int c = jj % CCH;
            float bias = (part == 0) ? __ldg(&qb[c]) : ((part == 2) ? __ldg(&vb[c]) : 0.f);
            float val = (acc[i][j] + bias) * __ldg(&ssc[jj]) + __ldg(&ssh[jj]);
            const int h = c / DHH, d = c % DHH;
            const size_t o = ((((size_t)b * HH + h) * NTOK) + n) * DHH + d;
            if (part == 0)       g_q[o] = val * QSCALE;
            else if (part == 1)  g_k[o] = val;
            else                 g_v[o] = val;
        }
    }
}

// ============================================================================
// K2: scores[bh,n,m] = q[bh,n,:]·k[bh,m,:] + rel_bias_table[rel_index[n,m], h]
// 32x32 tiles over (n,m), full K=64
// ============================================================================
__global__ __launch_bounds__(256) void scores_kernel(
    const float* __restrict__ relTab, const int* __restrict__ relIdx)
{
    const int bh = blockIdx.z;
    const int h  = bh % HH;
    const int n0 = blockIdx.y * 32;
    const int m0 = blockIdx.x * 32;

    __shared__ float Qs[32][65];
    __shared__ float Ks[32][65];

    const float* qp = g_q + (size_t)bh * NTOK * DHH;
    const float* kp = g_k + (size_t)bh * NTOK * DHH;

    const int tid = threadIdx.x;
    for (int i = tid; i < 32 * 16; i += 256) {
        const int r = i / 16, c4 = i % 16;
        float4 qv = {0, 0, 0, 0}, kv = {0, 0, 0, 0};
        if (n0 + r < NTOK) qv = *(const float4*)&qp[(size_t)(n0 + r) * DHH + c4 * 4];
        if (m0 + r < NTOK) kv = *(const float4*)&kp[(size_t)(m0 + r) * DHH + c4 * 4];
        Qs[r][c4 * 4 + 0] = qv.x; Qs[r][c4 * 4 + 1] = qv.y;
        Qs[r][c4 * 4 + 2] = qv.z; Qs[r][c4 * 4 + 3] = qv.w;
        Ks[r][c4 * 4 + 0] = kv.x; Ks[r][c4 * 4 + 1] = kv.y;
        Ks[r][c4 * 4 + 2] = kv.z; Ks[r][c4 * 4 + 3] = kv.w;
    }
    __syncthreads();

    const int ty = tid / 16, tx = tid % 16;   // each thread: 2x2 outputs
    float acc[2][2] = {};
#pragma unroll
    for (int d = 0; d < 64; d++) {
        const float a0 = Qs[ty * 2 + 0][d];
        const float a1 = Qs[ty * 2 + 1][d];
        const float b0 = Ks[tx * 2 + 0][d];
        const float b1 = Ks[tx * 2 + 1][d];
        acc[0][0] = fmaf(a0, b0, acc[0][0]);
        acc[0][1] = fmaf(a0, b1, acc[0][1]);
        acc[1][0] = fmaf(a1, b0, acc[1][0]);
        acc[1][1] = fmaf(a1, b1, acc[1][1]);
    }

#pragma unroll
    for (int i = 0; i < 2; i++) {
        const int n = n0 + ty * 2 + i;
        if (n >= NTOK) continue;
#pragma unroll
        for (int j = 0; j < 2; j++) {
            const int m = m0 + tx * 2 + j;
            if (m >= NTOK) continue;
            const int ri = __ldg(&relIdx[n * NTOK + m]);
            const float bias = __ldg(&relTab[ri * HH + h]);
            g_sc[((size_t)bh * NTOK + n) * NTOK + m] = acc[i][j] + bias;
        }
    }
}

// ============================================================================
// K3: per (b,n): softmax over m for all 12 heads, then DCF mix across heads
//     g_am[b,k,n,m] = sum_h (coeff[k,h] + (h==k)) * softmax(scores[b,h,n,:])[m]
// 384 threads = 12 warps; warp w owns head w for the softmax phase.
// ============================================================================
__global__ __launch_bounds__(384) void softmax_mix(const float* __restrict__ coeff)
{
    const int bn = blockIdx.x;
    const int b = bn / NTOK, n = bn % NTOK;

    __shared__ float P[HH][200];
    __shared__ float mixs[HH][HH];   // mixs[h][k]

    const int tid = threadIdx.x;
    if (tid < HH * HH) {
        const int k = tid / HH, h = tid % HH;
        mixs[h][k] = __ldg(&coeff[k * HH + h]) + (h == k ? 1.f : 0.f);
    }
    for (int e = tid; e < HH * NTOK; e += 384) {
        const int h = e / NTOK, m = e % NTOK;
        P[h][m] = g_sc[(((size_t)b * HH + h) * NTOK + n) * NTOK + m];
    }
    __syncthreads();

    {
        const int w = tid / 32, lane = tid % 32;   // 12 warps, head w
        float mx = -1e30f;
        for (int m = lane; m < NTOK; m += 32) mx = fmaxf(mx, P[w][m]);
#pragma unroll
        for (int o = 16; o; o >>= 1) mx = fmaxf(mx, __shfl_xor_sync(0xffffffffu, mx, o));
        float sum = 0.f;
        for (int m = lane; m < NTOK; m += 32) {
            const float e = __expf(P[w][m] - mx);
            P[w][m] = e;
            sum += e;
        }
#pragma unroll
        for (int o = 16; o; o >>= 1) sum += __shfl_xor_sync(0xffffffffu, sum, o);
        const float inv = 1.f / sum;
        for (int m = lane; m < NTOK; m += 32) P[w][m] *= inv;
    }
    __syncthreads();

    for (int e = tid; e < HH * NTOK; e += 384) {
        const int k = e / NTOK, m = e % NTOK;
        float acc = 0.f;
#pragma unroll
        for (int h = 0; h < HH; h++) acc = fmaf(mixs[h][k], P[h][m], acc);
        g_am[(((size_t)b * HH + k) * NTOK + n) * NTOK + m] = acc;
    }
}

// ============================================================================
// K4: ctx[b,n,h,d] = sum_m g_am[b,h,n,m] * g_v[b,h,m,d]
// per (b,h): [197,197] @ [197,64]; 32-row output tiles, BK=32
// ============================================================================
__global__ __launch_bounds__(256) void av_gemm()
{
    const int bh = blockIdx.z;
    const int b = bh / HH, h = bh % HH;
    const int n0 = blockIdx.y * 32;

    __shared__ float As[32][33];
    __shared__ float Vs[32][64];

    const float* A = g_am + (size_t)bh * NTOK * NTOK;
    const float* V = g_v  + (size_t)bh * NTOK * DHH;

    const int tid = threadIdx.x;
    const int ty = tid / 16, tx = tid % 16;   // rows ty*2+{0,1}, cols tx*4..+3
    float acc[2][4] = {};

    for (int m0 = 0; m0 < NTOK; m0 += 32) {
        for (int i = tid; i < 32 * 32; i += 256) {
            const int r = i / 32, c = i % 32;
            float vA = 0.f;
            if (n0 + r < NTOK && m0 + c < NTOK)
                vA = A[(size_t)(n0 + r) * NTOK + m0 + c];
            As[r][c] = vA;
        }
        for (int i = tid; i < 32 * 16; i += 256) {
            const int r = i / 16, c4 = i % 16;
            float4 vv = {0, 0, 0, 0};
            if (m0 + r < NTOK) vv = *(const float4*)&V[(size_t)(m0 + r) * DHH + c4 * 4];
            Vs[r][c4 * 4 + 0] = vv.x; Vs[r][c4 * 4 + 1] = vv.y;
            Vs[r][c4 * 4 + 2] = vv.z; Vs[r][c4 * 4 + 3] = vv.w;
        }
        __syncthreads();
#pragma unroll
        for (int mm = 0; mm < 32; mm++) {
            const float a0 = As[ty * 2 + 0][mm];
            const float a1 = As[ty * 2 + 1][mm];
            float4 v4 = *(const float4*)&Vs[mm][tx * 4];
            acc[0][0] = fmaf(a0, v4.x, acc[0][0]);
            acc[0][1] = fmaf(a0, v4.y, acc[0][1]);
            acc[0][2] = fmaf(a0, v4.z, acc[0][2]);
            acc[0][3] = fmaf(a0, v4.w, acc[0][3]);
            acc[1][0] = fmaf(a1, v4.x, acc[1][0]);
            acc[1][1] = fmaf(a1, v4.y, acc[1][1]);
            acc[1][2] = fmaf(a1, v4.z, acc[1][2]);
            acc[1][3] = fmaf(a1, v4.w, acc[1][3]);
        }
        __syncthreads();
    }

#pragma unroll
    for (int i = 0; i < 2; i++) {
        const int n = n0 + ty * 2 + i;
        if (n >= NTOK) continue;
        float4 o4 = {acc[i][0], acc[i][1], acc[i][2], acc[i][3]};
        *(float4*)&g_ctx[(((size_t)(b * NTOK + n)) * HH + h) * DHH + tx * 4] = o4;
    }
}

// ============================================================================
// K5: out = ctx @ proj_w^T + proj_b, then SSF
// Same GEMM structure as K1. M=12608, N=768, K=768.
// ============================================================================
__global__ __launch_bounds__(256) void proj_gemm(
    const float* __restrict__ w, const float* __restrict__ pb,
    const float* __restrict__ scp, const float* __restrict__ shp,
    float* __restrict__ out)
{
    __shared__ float As[16][64];
    __shared__ float Bs[16][64];

    const int tid = threadIdx.x;
    const int m0 = blockIdx.y * 64;
    const int j0 = blockIdx.x * 64;

    const int tr = tid / 16, tc = tid % 16;
    const int lr = tid / 4,  lc = tid % 4;

    const float* arow = g_ctx + (size_t)(m0 + lr) * CCH + lc * 4;
    const float* wrow = w + (size_t)(j0 + lr) * CCH + lc * 4;

    float acc[4][4] = {};

    for (int k0 = 0; k0 < CCH; k0 += 16) {
        float4 av = *(const float4*)(arow + k0);
        float4 bv = *(const float4*)(wrow + k0);
        As[lc * 4 + 0][lr] = av.x; As[lc * 4 + 1][lr] = av.y;
        As[lc * 4 + 2][lr] = av.z; As[lc * 4 + 3][lr] = av.w;
        Bs[lc * 4 + 0][lr] = bv.x; Bs[lc * 4 + 1][lr] = bv.y;
        Bs[lc * 4 + 2][lr] = bv.z; Bs[lc * 4 + 3][lr] = bv.w;
        __syncthreads();
#pragma unroll
        for (int kk = 0; kk < 16; kk++) {
            float4 a4 = *(const float4*)&As[kk][tr * 4];
            float4 b4 = *(const float4*)&Bs[kk][tc * 4];
            float a[4] = {a4.x, a4.y, a4.z, a4.w};
            float b[4] = {b4.x, b4.y, b4.z, b4.w};
#pragma unroll
            for (int i = 0; i < 4; i++)
#pragma unroll
                for (int j = 0; j < 4; j++)
                    acc[i][j] = fmaf(a[i], b[j], acc[i][j]);
        }
        __syncthreads();
    }

#pragma unroll
    for (int i = 0; i < 4; i++) {
        const int m = m0 + tr * 4 + i;
#pragma unroll
        for (int j = 0; j < 4; j++) {
            const int jj = j0 + tc * 4 + j;
            out[(size_t)m * CCH + jj] = (acc[i][j] + __ldg(&pb[jj])) * __ldg(&scp[jj]) + __ldg(&shp[jj]);
        }
    }
}

// ============================================================================
extern "C" void kernel_launch(void* const* d_in, const int* in_sizes, int n_in,
                              void* d_out, int out_size)
{
    const float* x       = (const float*)d_in[0];
    const float* qkv_w   = (const float*)d_in[1];
    const float* q_bias  = (const float*)d_in[2];
    const float* v_bias  = (const float*)d_in[3];
    const float* ssc_qkv = (const float*)d_in[4];
    const float* ssh_qkv = (const float*)d_in[5];
    const float* relTab  = (const float*)d_in[6];
    const float* coeff   = (const float*)d_in[7];
    const float* proj_w  = (const float*)d_in[8];
    const float* proj_b  = (const float*)d_in[9];
    const float* scp     = (const float*)d_in[10];
    const float* shp     = (const float*)d_in[11];
    const int*   relIdx  = (const int*)d_in[12];
    float* out = (float*)d_out;

    qkv_gemm<<<dim3(C3 / 64, MTOK / 64), 256>>>(x, qkv_w, q_bias, v_bias, ssc_qkv, ssh_qkv);
    scores_kernel<<<dim3(7, 7, BB * HH), 256>>>(relTab, relIdx);
    softmax_mix<<<MTOK, 384>>>(coeff);
    av_gemm<<<dim3(1, 7, BB * HH), 256>>>();
    proj_gemm<<<dim3(CCH / 64, MTOK / 64), 256>>>(proj_w, proj_b, scp, shp, out);
}

// round 3
// speedup vs baseline: 2.0501x; 2.0501x over previous
#include <cuda_runtime.h>
#include <math.h>
#include <stdint.h>

// Problem constants
#define BB   64
#define NTOK 197
#define CCH  768
#define HH   12
#define DHH  64
#define C3   2304
#define MTOK (BB * NTOK)          // 12608
#define QSCALE 0.125f             // 64^-0.5

// -------- device scratch --------
__device__ float g_q[(size_t)BB * HH * NTOK * DHH];
__device__ float g_k[(size_t)BB * HH * NTOK * DHH];
__device__ float g_v[(size_t)BB * HH * NTOK * DHH];
__device__ float g_sc[(size_t)BB * HH * NTOK * NTOK];
__device__ float g_am[(size_t)BB * HH * NTOK * NTOK];
__device__ float g_ctx[(size_t)MTOK * CCH];

// ---------------- tf32 helpers ----------------
__device__ __forceinline__ uint32_t f2tf(float f) {
    uint32_t u;
    asm("cvt.rna.tf32.f32 %0, %1;" : "=r"(u) : "f"(f));
    return u;
}
__device__ __forceinline__ void mma_tf32(float c[4],
                                         uint32_t a0, uint32_t a1, uint32_t a2, uint32_t a3,
                                         uint32_t b0, uint32_t b1) {
    asm volatile(
        "mma.sync.aligned.m16n8k8.row.col.f32.tf32.tf32.f32 "
        "{%0,%1,%2,%3}, {%4,%5,%6,%7}, {%8,%9}, {%0,%1,%2,%3};"
        : "+f"(c[0]), "+f"(c[1]), "+f"(c[2]), "+f"(c[3])
        : "r"(a0), "r"(a1), "r"(a2), "r"(a3), "r"(b0), "r"(b1));
}

// ============================================================================
// tf32 GEMM mainloop (shared by K1/K5):
//   C[128x128] tile of  A[M,768] @ W[N,768]^T
// 8 warps: warp_m = wid%4 (32 rows), warp_n = wid/4 (64 cols)
// smem stride 20 words -> conflict-free fragment loads
// ============================================================================
#define SMS 20   // smem row stride (16 cols + 4 pad)

struct FragAcc { float a[2][8][4]; };

__device__ __forceinline__ void gemm_tf32_mainloop(
    const float* __restrict__ A, const float* __restrict__ W,
    int m0, int j0, FragAcc& F)
{
    __shared__ uint32_t As[2][128][SMS];
    __shared__ uint32_t Bs[2][128][SMS];

    const int tid  = threadIdx.x;
    const int wid  = tid / 32, lane = tid % 32;
    const int wm   = (wid % 4) * 32;
    const int wn   = (wid / 4) * 64;
    const int lr   = tid / 4;           // 0..63
    const int c0   = (tid % 4) * 4;     // 0,4,8,12

    const int ar0 = m0 + lr, ar1 = m0 + 64 + lr;     // A rows (guard vs MTOK)
    const float* ap0 = A + (size_t)ar0 * CCH + c0;
    const float* ap1 = A + (size_t)ar1 * CCH + c0;
    const float* bp0 = W + (size_t)(j0 + lr) * CCH + c0;
    const float* bp1 = W + (size_t)(j0 + 64 + lr) * CCH + c0;
    const bool v0 = ar0 < MTOK, v1 = ar1 < MTOK;

    float4 at0, at1, bt0, bt1;
    const float4 z4 = {0.f, 0.f, 0.f, 0.f};

    // preload k0 = 0
    at0 = v0 ? *(const float4*)ap0 : z4;
    at1 = v1 ? *(const float4*)ap1 : z4;
    bt0 = *(const float4*)bp0;
    bt1 = *(const float4*)bp1;
    {
        uint4 u;
        u.x = f2tf(at0.x); u.y = f2tf(at0.y); u.z = f2tf(at0.z); u.w = f2tf(at0.w);
        *(uint4*)&As[0][lr][c0] = u;
        u.x = f2tf(at1.x); u.y = f2tf(at1.y); u.z = f2tf(at1.z); u.w = f2tf(at1.w);
        *(uint4*)&As[0][64 + lr][c0] = u;
        u.x = f2tf(bt0.x); u.y = f2tf(bt0.y); u.z = f2tf(bt0.z); u.w = f2tf(bt0.w);
        *(uint4*)&Bs[0][lr][c0] = u;
        u.x = f2tf(bt1.x); u.y = f2tf(bt1.y); u.z = f2tf(bt1.z); u.w = f2tf(bt1.w);
        *(uint4*)&Bs[0][64 + lr][c0] = u;
    }
    __syncthreads();

    int buf = 0;
    const int gid = lane >> 2;   // 0..7
    const int qid = lane & 3;    // 0..3

    for (int k0 = 0; k0 < CCH; k0 += 16) {
        const bool more = (k0 + 16) < CCH;
        if (more) {
            const int kn = k0 + 16;
            at0 = v0 ? *(const float4*)(ap0 + kn) : z4;
            at1 = v1 ? *(const float4*)(ap1 + kn) : z4;
            bt0 = *(const float4*)(bp0 + kn);
            bt1 = *(const float4*)(bp1 + kn);
        }

#pragma unroll
        for (int kk = 0; kk < 16; kk += 8) {
            uint32_t afr[2][4];
#pragma unroll
            for (int i = 0; i < 2; i++) {
                const int r = wm + i * 16 + gid;
                afr[i][0] = As[buf][r][kk + qid];
                afr[i][1] = As[buf][r + 8][kk + qid];
                afr[i][2] = As[buf][r][kk + 4 + qid];
                afr[i][3] = As[buf][r + 8][kk + 4 + qid];
            }
#pragma unroll
            for (int j = 0; j < 8; j++) {
                const int nc = wn + j * 8 + gid;
                const uint32_t b0 = Bs[buf][nc][kk + qid];
                const uint32_t b1 = Bs[buf][nc][kk + 4 + qid];
#pragma unroll
                for (int i = 0; i < 2; i++)
                    mma_tf32(F.a[i][j], afr[i][0], afr[i][1], afr[i][2], afr[i][3], b0, b1);
            }
        }

        if (more) {
            const int nb = buf ^ 1;
            uint4 u;
            u.x = f2tf(at0.x); u.y = f2tf(at0.y); u.z = f2tf(at0.z); u.w = f2tf(at0.w);
            *(uint4*)&As[nb][lr][c0] = u;
            u.x = f2tf(at1.x); u.y = f2tf(at1.y); u.z = f2tf(at1.z); u.w = f2tf(at1.w);
            *(uint4*)&As[nb][64 + lr][c0] = u;
            u.x = f2tf(bt0.x); u.y = f2tf(bt0.y); u.z = f2tf(bt0.z); u.w = f2tf(bt0.w);
            *(uint4*)&Bs[nb][lr][c0] = u;
            u.x = f2tf(bt1.x); u.y = f2tf(bt1.y); u.z = f2tf(bt1.z); u.w = f2tf(bt1.w);
            *(uint4*)&Bs[nb][64 + lr][c0] = u;
        }
        __syncthreads();
        buf ^= 1;
    }
}

// ============================================================================
// K1: QKV projection (tf32 tensor cores) + bias/SSF epilogue + scatter
// ============================================================================
__device__ __forceinline__ void qkv_store_one(
    int m, int jj, float a,
    const float* __restrict__ qb, const float* __restrict__ vb,
    const float* __restrict__ ssc, const float* __restrict__ ssh)
{
    if (m >= MTOK) return;
    const int part = jj / CCH;
    const int c = jj % CCH;
    float bias = (part == 0) ? __ldg(qb + c) : ((part == 2) ? __ldg(vb + c) : 0.f);
    float val = (a + bias) * __ldg(ssc + jj) + __ldg(ssh + jj);
    const int b = m / NTOK, n = m % NTOK, h = c / DHH, d = c % DHH;
    const size_t o = ((((size_t)b * HH + h) * NTOK) + n) * DHH + d;
    if (part == 0)       g_q[o] = val * QSCALE;
    else if (part == 1)  g_k[o] = val;
    else                 g_v[o] = val;
}

__global__ __launch_bounds__(256) void qkv_gemm_tf32(
    const float* __restrict__ x, const float* __restrict__ w,
    const float* __restrict__ qb, const float* __restrict__ vb,
    const float* __restrict__ ssc, const float* __restrict__ ssh)
{
    const int m0 = blockIdx.y * 128;
    const int j0 = blockIdx.x * 128;

    FragAcc F;
#pragma unroll
    for (int i = 0; i < 2; i++)
#pragma unroll
        for (int j = 0; j < 8; j++)
#pragma unroll
            for (int c = 0; c < 4; c++) F.a[i][j][c] = 0.f;

    gemm_tf32_mainloop(x, w, m0, j0, F);

    const int tid = threadIdx.x, wid = tid / 32, lane = tid % 32;
    const int wm = (wid % 4) * 32, wn = (wid / 4) * 64;
#pragma unroll
    for (int i = 0; i < 2; i++) {
        const int r = m0 + wm + i * 16 + (lane >> 2);
#pragma unroll
        for (int j = 0; j < 8; j++) {
            const int col = j0 + wn + j * 8 + (lane & 3) * 2;
            qkv_store_one(r,     col,     F.a[i][j][0], qb, vb, ssc, ssh);
            qkv_store_one(r,     col + 1, F.a[i][j][1], qb, vb, ssc, ssh);
            qkv_store_one(r + 8, col,     F.a[i][j][2], qb, vb, ssc, ssh);
            qkv_store_one(r + 8, col + 1, F.a[i][j][3], qb, vb, ssc, ssh);
        }
    }
}

// ============================================================================
// K5: proj (tf32 tensor cores) + bias + SSF
// ============================================================================
__global__ __launch_bounds__(256) void proj_gemm_tf32(
    const float* __restrict__ w, const float* __restrict__ pb,
    const float* __restrict__ scp, const float* __restrict__ shp,
    float* __restrict__ out)
{
    const int m0 = blockIdx.y * 128;
    const int j0 = blockIdx.x * 128;

    FragAcc F;
#pragma unroll
    for (int i = 0; i < 2; i++)
#pragma unroll
        for (int j = 0; j < 8; j++)
#pragma unroll
            for (int c = 0; c < 4; c++) F.a[i][j][c] = 0.f;

    gemm_tf32_mainloop(g_ctx, w, m0, j0, F);

    const int tid = threadIdx.x, wid = tid / 32, lane = tid % 32;
    const int wm = (wid % 4) * 32, wn = (wid / 4) * 64;
#pragma unroll
    for (int i = 0; i < 2; i++) {
#pragma unroll
        for (int rr = 0; rr < 2; rr++) {
            const int m = m0 + wm + i * 16 + (lane >> 2) + rr * 8;
            if (m >= MTOK) continue;
#pragma unroll
            for (int j = 0; j < 8; j++) {
                const int col = j0 + wn + j * 8 + (lane & 3) * 2;
                const float v0 = F.a[i][j][rr * 2 + 0];
                const float v1 = F.a[i][j][rr * 2 + 1];
                out[(size_t)m * CCH + col]     = (v0 + __ldg(pb + col))     * __ldg(scp + col)     + __ldg(shp + col);
                out[(size_t)m * CCH + col + 1] = (v1 + __ldg(pb + col + 1)) * __ldg(scp + col + 1) + __ldg(shp + col + 1);
            }
        }
    }
}

// ============================================================================
// K2: scores = q@k^T + rel bias.  64x64 tiles, 4x4 per thread.
// ============================================================================
__global__ __launch_bounds__(256) void scores_kernel(
    const float* __restrict__ relTab, const int* __restrict__ relIdx)
{
    const int bh = blockIdx.z;
    const int h  = bh % HH;
    const int n0 = blockIdx.y * 64;
    const int m0 = blockIdx.x * 64;

    __shared__ float Qs[64][65];
    __shared__ float Ks[64][65];

    const float* qp = g_q + (size_t)bh * NTOK * DHH;
    const float* kp = g_k + (size_t)bh * NTOK * DHH;

    const int tid = threadIdx.x;
    for (int i = tid; i < 64 * 16; i += 256) {
        const int r = i / 16, c4 = i % 16;
        float4 qv = {0, 0, 0, 0}, kv = {0, 0, 0, 0};
        if (n0 + r < NTOK) qv = *(const float4*)&qp[(size_t)(n0 + r) * DHH + c4 * 4];
        if (m0 + r < NTOK) kv = *(const float4*)&kp[(size_t)(m0 + r) * DHH + c4 * 4];
        Qs[r][c4 * 4 + 0] = qv.x; Qs[r][c4 * 4 + 1] = qv.y;
        Qs[r][c4 * 4 + 2] = qv.z; Qs[r][c4 * 4 + 3] = qv.w;
        Ks[r][c4 * 4 + 0] = kv.x; Ks[r][c4 * 4 + 1] = kv.y;
        Ks[r][c4 * 4 + 2] = kv.z; Ks[r][c4 * 4 + 3] = kv.w;
    }
    __syncthreads();

    const int ty = tid / 16, tx = tid % 16;
    float acc[4][4] = {};
#pragma unroll
    for (int d = 0; d < 64; d++) {
        float a[4], b[4];
#pragma unroll
        for (int i = 0; i < 4; i++) a[i] = Qs[ty * 4 + i][d];
#pragma unroll
        for (int j = 0; j < 4; j++) b[j] = Ks[tx * 4 + j][d];
#pragma unroll
        for (int i = 0; i < 4; i++)
#pragma unroll
            for (int j = 0; j < 4; j++)
                acc[i][j] = fmaf(a[i], b[j], acc[i][j]);
    }

#pragma unroll
    for (int i = 0; i < 4; i++) {
        const int n = n0 + ty * 4 + i;
        if (n >= NTOK) continue;
#pragma unroll
        for (int j = 0; j < 4; j++) {
            const int m = m0 + tx * 4 + j;
            if (m >= NTOK) continue;
            const int ri = __ldg(&relIdx[n * NTOK + m]);
            g_sc[((size_t)bh * NTOK + n) * NTOK + m] = acc[i][j] + __ldg(&relTab[ri * HH + h]);
        }
    }
}

// ============================================================================
// K3: softmax over m for all 12 heads, then DCF mix across heads
// ============================================================================
__global__ __launch_bounds__(384) void softmax_mix(const float* __restrict__ coeff)
{
    const int bn = blockIdx.x;
    const int b = bn / NTOK, n = bn % NTOK;

    __shared__ float P[HH][200];
    __shared__ float mixs[HH][HH];

    const int tid = threadIdx.x;
    if (tid < HH * HH) {
        const int k = tid / HH, h = tid % HH;
        mixs[h][k] = __ldg(&coeff[k * HH + h]) + (h == k ? 1.f : 0.f);
    }
    for (int e = tid; e < HH * NTOK; e += 384) {
        const int h = e / NTOK, m = e % NTOK;
        P[h][m] = g_sc[(((size_t)b * HH + h) * NTOK + n) * NTOK + m];
    }
    __syncthreads();

    {
        const int w = tid / 32, lane = tid % 32;
        float mx = -1e30f;
        for (int m = lane; m < NTOK; m += 32) mx = fmaxf(mx, P[w][m]);
#pragma unroll
        for (int o = 16; o; o >>= 1) mx = fmaxf(mx, __shfl_xor_sync(0xffffffffu, mx, o));
        float sum = 0.f;
        for (int m = lane; m < NTOK; m += 32) {
            const float e = __expf(P[w][m] - mx);
            P[w][m] = e;
            sum += e;
        }
#pragma unroll
        for (int o = 16; o; o >>= 1) sum += __shfl_xor_sync(0xffffffffu, sum, o);
        const float inv = 1.f / sum;
        for (int m = lane; m < NTOK; m += 32) P[w][m] *= inv;
    }
    __syncthreads();

    for (int e = tid; e < HH * NTOK; e += 384) {
        const int k = e / NTOK, m = e % NTOK;
        float acc = 0.f;
#pragma unroll
        for (int h = 0; h < HH; h++) acc = fmaf(mixs[h][k], P[h][m], acc);
        g_am[(((size_t)b * HH + k) * NTOK + n) * NTOK + m] = acc;
    }
}

// ============================================================================
// K4: ctx = attn @ v.  64-row tiles, 4x4 per thread.
// ============================================================================
__global__ __launch_bounds__(256) void av_gemm()
{
    const int bh = blockIdx.z;
    const int b = bh / HH, h = bh % HH;
    const int n0 = blockIdx.y * 64;

    __shared__ float As[64][33];
    __shared__ float Vs[32][68];

    const float* A = g_am + (size_t)bh * NTOK * NTOK;
    const float* V = g_v  + (size_t)bh * NTOK * DHH;

    const int tid = threadIdx.x;
    const int ty = tid / 16, tx = tid % 16;
    float acc[4][4] = {};

    for (int m0 = 0; m0 < NTOK; m0 += 32) {
        for (int i = tid; i < 64 * 8; i += 256) {
            const int r = i / 8, cb = (i % 8) * 4;
#pragma unroll
            for (int c = 0; c < 4; c++) {
                float vA = 0.f;
                if (n0 + r < NTOK && m0 + cb + c < NTOK)
                    vA = A[(size_t)(n0 + r) * NTOK + m0 + cb + c];
                As[r][cb + c] = vA;
            }
        }
        for (int i = tid; i < 32 * 16; i += 256) {
            const int r = i / 16, c4 = i % 16;
            float4 vv = {0, 0, 0, 0};
            if (m0 + r < NTOK) vv = *(const float4*)&V[(size_t)(m0 + r) * DHH + c4 * 4];
            Vs[r][c4 * 4 + 0] = vv.x; Vs[r][c4 * 4 + 1] = vv.y;
            Vs[r][c4 * 4 + 2] = vv.z; Vs[r][c4 * 4 + 3] = vv.w;
        }
        __syncthreads();
#pragma unroll
        for (int mm = 0; mm < 32; mm++) {
            float a[4];
#pragma unroll
            for (int i = 0; i < 4; i++) a[i] = As[ty * 4 + i][mm];
            float4 v4 = *(const float4*)&Vs[mm][tx * 4];
            const float bv[4] = {v4.x, v4.y, v4.z, v4.w};
#pragma unroll
            for (int i = 0; i < 4; i++)
#pragma unroll
                for (int j = 0; j < 4; j++)
                    acc[i][j] = fmaf(a[i], bv[j], acc[i][j]);
        }
        __syncthreads();
    }

#pragma unroll
    for (int i = 0; i < 4; i++) {
        const int n = n0 + ty * 4 + i;
        if (n >= NTOK) continue;
        float4 o4 = {acc[i][0], acc[i][1], acc[i][2], acc[i][3]};
        *(float4*)&g_ctx[(((size_t)(b * NTOK + n)) * HH + h) * DHH + tx * 4] = o4;
    }
}

// ============================================================================
extern "C" void kernel_launch(void* const* d_in, const int* in_sizes, int n_in,
                              void* d_out, int out_size)
{
    const float* x       = (const float*)d_in[0];
    const float* qkv_w   = (const float*)d_in[1];
    const float* q_bias  = (const float*)d_in[2];
    const float* v_bias  = (const float*)d_in[3];
    const float* ssc_qkv = (const float*)d_in[4];
    const float* ssh_qkv = (const float*)d_in[5];
    const float* relTab  = (const float*)d_in[6];
    const float* coeff   = (const float*)d_in[7];
    const float* proj_w  = (const float*)d_in[8];
    const float* proj_b  = (const float*)d_in[9];
    const float* scp     = (const float*)d_in[10];
    const float* shp     = (const float*)d_in[11];
    const int*   relIdx  = (const int*)d_in[12];
    float* out = (float*)d_out;

    qkv_gemm_tf32<<<dim3(C3 / 128, (MTOK + 127) / 128), 256>>>(x, qkv_w, q_bias, v_bias, ssc_qkv, ssh_qkv);
    scores_kernel<<<dim3(4, 4, BB * HH), 256>>>(relTab, relIdx);
    softmax_mix<<<MTOK, 384>>>(coeff);
    av_gemm<<<dim3(1, 4, BB * HH), 256>>>();
    proj_gemm_tf32<<<dim3(CCH / 128, (MTOK + 127) / 128), 256>>>(proj_w, proj_b, scp, shp, out);
}